// round 14
// baseline (speedup 1.0000x reference)
#include <cuda_runtime.h>
#include <cuda_fp16.h>
#include <cstdint>

#define SEQ 4096
#define EMB 1024

// ---------------- scratch (static, allocation-free) ----------------
__device__ __half g_Xh [(size_t)SEQ * EMB];
__device__ __half g_Wqh[(size_t)EMB * EMB];   // fp16(Wq), row-major
__device__ __half g_Wkh[(size_t)EMB * EMB];   // fp16(Wk), row-major
__device__ __half g_Wvt[(size_t)EMB * EMB];   // fp16(Wv^T)
__device__ __half g_M  [(size_t)EMB * EMB];   // Wq @ Wk^T
__device__ __half g_Tt [(size_t)SEQ * EMB];   // X @ M^T   (== (Q K^T)-operand)
__device__ __half g_Vt [(size_t)EMB * SEQ];   // Wv^T @ X^T == V^T
__device__ __half g_Sh [(size_t)SEQ * SEQ];
__device__ float  g_part[(size_t)SEQ * 64];   // per (row, colCTA*2+wn) partials
// counters: [0]=mDone(64), [1..32]=ttReady(8), [33..40]=vtReady(32), [41..72]=ready(32)
__device__ unsigned int g_cnt[73];

// ---------------- helpers ----------------
__device__ __forceinline__ uint32_t smem_u32(const void* p) {
    return (uint32_t)__cvta_generic_to_shared(p);
}
__device__ __forceinline__ void cp16(uint32_t s, const void* g) {
    asm volatile("cp.async.cg.shared.global [%0], [%1], 16;" :: "r"(s), "l"(g));
}
__device__ __forceinline__ void cp_commit() {
    asm volatile("cp.async.commit_group;" ::: "memory");
}
template <int N>
__device__ __forceinline__ void cp_wait() {
    asm volatile("cp.async.wait_group %0;" :: "n"(N) : "memory");
}
__device__ __forceinline__ float ex2_mufu(float y) {
    float r;
    asm("ex2.approx.ftz.f32 %0, %1;" : "=f"(r) : "f"(y));
    return r;
}
// exact-split exp2 on the FMA pipe (y = n + f, f in [-.5,.5], degree-5 poly)
__device__ __forceinline__ float ex2_fma(float y) {
    const float MAGIC = 12582912.0f;          // 1.5 * 2^23
    float tm = __fadd_rn(y, MAGIC);
    float f  = __fadd_rn(y, -__fadd_rn(tm, -MAGIC));
    int   eb = (__float_as_int(tm) << 23) + 0x3F800000;
    float pl = 0.0013333558f;
    pl = fmaf(pl, f, 0.0096181291f);
    pl = fmaf(pl, f, 0.0555041087f);
    pl = fmaf(pl, f, 0.2402265069f);
    pl = fmaf(pl, f, 0.6931471806f);
    pl = fmaf(pl, f, 1.0f);
    return __int_as_float(eb) * pl;
}
// m16n8k16 fp16 MMA, fp32 accumulate
__device__ __forceinline__ void mma_f16(
    float& c0, float& c1, float& c2, float& c3,
    uint32_t a0, uint32_t a1, uint32_t a2, uint32_t a3,
    uint32_t b0, uint32_t b1)
{
    asm volatile(
        "mma.sync.aligned.m16n8k16.row.col.f32.f16.f16.f32 "
        "{%0,%1,%2,%3}, {%4,%5,%6,%7}, {%8,%9}, {%0,%1,%2,%3};"
        : "+f"(c0), "+f"(c1), "+f"(c2), "+f"(c3)
        : "r"(a0), "r"(a1), "r"(a2), "r"(a3), "r"(b0), "r"(b1));
}

// spin until counter >= target, then acquire-fence + block barrier
__device__ __forceinline__ void wait_cnt(unsigned int* c, unsigned int target) {
    if (threadIdx.x == 0) {
        while (atomicAdd(c, 0u) < target) __nanosleep(100);
        __threadfence();
    }
    __syncthreads();
}
// release: fence all threads' stores, then bump counter
__device__ __forceinline__ void signal_cnt(unsigned int* c) {
    __threadfence();
    __syncthreads();
    if (threadIdx.x == 0) atomicAdd(c, 1u);
}

// ---------------------------------------------------------------------------
// FP16 tensor-core NT GEMM: C[M,N] = f( A[M,K] @ B[N,K]^T )
// 128 threads (4 warps 2x2), warp tile 64x64, CTA tile 128x128, BK=64,
// 3-stage cp.async, one __syncthreads/iter, XOR-swizzled smem,
// scalar-LDS fragment loads (known-good mainloop).
// MODE 0: fp16 out
// MODE 1: Sh = fp16(exp(alpha*acc)); per-(row,warp) partial sums -> part
// MODE 2: fp32 out scaled by rsum computed in prologue from part
// ---------------------------------------------------------------------------
#define STG 3
#define OPW (128 * 32)                 // fp16x2 words per operand tile (16KB)
#define STW (2 * OPW)
#define GEMM_DYNSMEM (STG * STW * 4)   // 98304 bytes

template <int MODE>
__device__ __forceinline__ void gemm_body(
    const __half* __restrict__ A, const __half* __restrict__ B,
    void* __restrict__ Cv, int N, int K, float alpha,
    float* __restrict__ part, int bm, int bn, int bx)
{
    extern __shared__ uint32_t sm[];
    __shared__ float rsm[128];

    const int tid  = threadIdx.x;
    const int warp = tid >> 5;
    const int lane = tid & 31;
    const int g    = lane >> 2;
    const int t    = lane & 3;
    const int wm   = warp & 1;      // 2 x 64 rows
    const int wn   = warp >> 1;     // 2 x 64 cols

    // MODE 2 prologue: reciprocal row sums for this CTA's 128 rows
    // (fixed-order 64-term sum -> deterministic). Covered by iter-0 barrier.
    if (MODE == 2) {
        const float4* pp = reinterpret_cast<const float4*>(
            part + (size_t)(bm + tid) * 64);
        float s = 0.0f;
        #pragma unroll
        for (int i = 0; i < 16; i++) {
            float4 v = pp[i];
            s += (v.x + v.y) + (v.z + v.w);
        }
        rsm[tid] = 1.0f / s;
    }

    float acc[4][8][4];
    #pragma unroll
    for (int mi = 0; mi < 4; mi++)
        #pragma unroll
        for (int ni = 0; ni < 8; ni++)
            #pragma unroll
            for (int r = 0; r < 4; r++) acc[mi][ni][r] = 0.0f;

    const uint32_t smb = smem_u32(sm);
    const int lrow = tid >> 3;          // 0..15, 8 passes -> 128 rows
    const int lseg = tid & 7;

    auto load_stage = [&](int chunk) {
        const int s  = chunk % STG;
        const int k0 = chunk * 64;
        const uint32_t sa = smb + s * (STW * 4);
        const uint32_t sb = sa + OPW * 4;
        #pragma unroll
        for (int p = 0; p < 8; p++) {
            const int row  = lrow + p * 16;
            const int segS = lseg ^ (row & 7);
            const uint32_t so = (uint32_t)(row * 128 + segS * 16);
            cp16(sa + so, A + (size_t)(bm + row) * K + k0 + lseg * 8);
            cp16(sb + so, B + (size_t)(bn + row) * K + k0 + lseg * 8);
        }
        cp_commit();
    };

    const int NT = K >> 6;

    load_stage(0);
    load_stage(1);

    for (int i = 0; i < NT; i++) {
        const int s = i % STG;
        cp_wait<1>();
        __syncthreads();

        if (i + 2 < NT) load_stage(i + 2);
        else            cp_commit();

        const uint32_t* As  = sm + s * STW;
        const uint32_t* Bsm = As + OPW;
        const int swz = 4 * g;

        #pragma unroll
        for (int ksi = 0; ksi < 4; ksi++) {
            const int c0 = (ksi * 8 + t)     ^ swz;
            const int c2 = (ksi * 8 + t + 4) ^ swz;

            uint32_t af[4][4];
            #pragma unroll
            for (int mi = 0; mi < 4; mi++) {
                const uint32_t* base = As + (wm * 64 + mi * 16 + g) * 32;
                af[mi][0] = base[c0];
                af[mi][1] = base[8 * 32 + c0];
                af[mi][2] = base[c2];
                af[mi][3] = base[8 * 32 + c2];
            }
            uint32_t bf[8][2];
            #pragma unroll
            for (int ni = 0; ni < 8; ni++) {
                const uint32_t* base = Bsm + (wn * 64 + ni * 8 + g) * 32;
                bf[ni][0] = base[c0];
                bf[ni][1] = base[c2];
            }
            #pragma unroll
            for (int mi = 0; mi < 4; mi++)
                #pragma unroll
                for (int ni = 0; ni < 8; ni++)
                    mma_f16(acc[mi][ni][0], acc[mi][ni][1],
                            acc[mi][ni][2], acc[mi][ni][3],
                            af[mi][0], af[mi][1], af[mi][2], af[mi][3],
                            bf[ni][0], bf[ni][1]);
        }
    }

    // ---- epilogue ----
    if (MODE == 0) {
        __half* C = (__half*)Cv;
        #pragma unroll
        for (int mi = 0; mi < 4; mi++) {
            const int row = bm + wm * 64 + mi * 16 + g;
            #pragma unroll
            for (int ni = 0; ni < 8; ni++) {
                const int col = bn + wn * 64 + ni * 8 + 2 * t;
                *reinterpret_cast<__half2*>(&C[(size_t)row * N + col]) =
                    __floats2half2_rn(acc[mi][ni][0], acc[mi][ni][1]);
                *reinterpret_cast<__half2*>(&C[(size_t)(row + 8) * N + col]) =
                    __floats2half2_rn(acc[mi][ni][2], acc[mi][ni][3]);
            }
        }
    } else if (MODE == 1) {
        __half* C = (__half*)Cv;
        const float aL = alpha * 1.4426950408889634f;   // alpha * log2(e)
        #pragma unroll
        for (int mi = 0; mi < 4; mi++) {
            const int row = bm + wm * 64 + mi * 16 + g;
            float sr0 = 0.0f, sr1 = 0.0f;
            #pragma unroll
            for (int ni = 0; ni < 8; ni++) {
                const int col = bn + wn * 64 + ni * 8 + 2 * t;
                float v0, v1, v2, v3;
                if (ni & 1) {                 // FMA pipe
                    v0 = ex2_fma(acc[mi][ni][0] * aL);
                    v1 = ex2_fma(acc[mi][ni][1] * aL);
                    v2 = ex2_fma(acc[mi][ni][2] * aL);
                    v3 = ex2_fma(acc[mi][ni][3] * aL);
                } else {                      // MUFU pipe
                    v0 = ex2_mufu(acc[mi][ni][0] * aL);
                    v1 = ex2_mufu(acc[mi][ni][1] * aL);
                    v2 = ex2_mufu(acc[mi][ni][2] * aL);
                    v3 = ex2_mufu(acc[mi][ni][3] * aL);
                }
                *reinterpret_cast<__half2*>(&C[(size_t)row * N + col]) =
                    __floats2half2_rn(v0, v1);
                *reinterpret_cast<__half2*>(&C[(size_t)(row + 8) * N + col]) =
                    __floats2half2_rn(v2, v3);
                sr0 += v0 + v1;
                sr1 += v2 + v3;
            }
            // sum over the 4 t-lanes (same g)
            sr0 += __shfl_xor_sync(0xFFFFFFFF, sr0, 1);
            sr0 += __shfl_xor_sync(0xFFFFFFFF, sr0, 2);
            sr1 += __shfl_xor_sync(0xFFFFFFFF, sr1, 1);
            sr1 += __shfl_xor_sync(0xFFFFFFFF, sr1, 2);
            if (t == 0) {
                part[(size_t)row * 64 + bx * 2 + wn]       = sr0;
                part[(size_t)(row + 8) * 64 + bx * 2 + wn] = sr1;
            }
        }
    } else {
        float* C = (float*)Cv;
        #pragma unroll
        for (int mi = 0; mi < 4; mi++) {
            const int lr  = wm * 64 + mi * 16 + g;
            const int row = bm + lr;
            const float s0 = rsm[lr];
            const float s1 = rsm[lr + 8];
            #pragma unroll
            for (int ni = 0; ni < 8; ni++) {
                const int col = bn + wn * 64 + ni * 8 + 2 * t;
                *reinterpret_cast<float2*>(&C[(size_t)row * N + col]) =
                    make_float2(acc[mi][ni][0] * s0, acc[mi][ni][1] * s0);
                *reinterpret_cast<float2*>(&C[(size_t)(row + 8) * N + col]) =
                    make_float2(acc[mi][ni][2] * s1, acc[mi][ni][3] * s1);
            }
        }
    }
}

// ---------------------------------------------------------------------------
// Mega kernel: all 5 GEMM stages in one launch, gated by readiness counters.
// Dependencies point strictly from higher bid to lower bid (dispatch order)
// -> guaranteed progress.
//   bid 0..63    : M  = Wq @ Wk^T                     -> cnt[0]        (64)
//   bid 64..319  : Tt = X @ M^T     (waits M)         -> cnt[1+byT]    (8)
//   bid 320..575 : Vt = Wv^T @ X^T                    -> cnt[33+bmV]   (32)
//   bid 576..1599: score (exp)      (waits Tt block)  -> cnt[41+by]    (32)
//   bid 1600..1855: pv              (waits score row-block + Vt block)
// ---------------------------------------------------------------------------
__global__ void __launch_bounds__(128, 2) mega_k(
    const __half* __restrict__ Xh,
    const __half* __restrict__ Wqh, const __half* __restrict__ Wkh,
    const __half* __restrict__ Wvt,
    __half* __restrict__ Mh, __half* __restrict__ Tt,
    __half* __restrict__ Vt, __half* __restrict__ Sh,
    float* __restrict__ part, float* __restrict__ out,
    unsigned int* __restrict__ cnt)
{
    const int bid = blockIdx.x;

    if (bid < 64) {
        // M = Wq @ Wk^T  (1024x1024, K=1024)
        const int bx = bid & 7, by = bid >> 3;
        gemm_body<0>(Wqh, Wkh, Mh, EMB, EMB, 1.0f, nullptr,
                     by * 128, bx * 128, bx);
        signal_cnt(&cnt[0]);
    } else if (bid < 320) {
        // Tt = X @ M^T  (4096x1024, K=1024); needs all of M
        const int tidx = bid - 64;
        const int bxT = tidx & 7;          // col block over 1024
        const int byT = tidx >> 3;         // row block over SEQ (0..31)
        wait_cnt(&cnt[0], 64u);
        gemm_body<0>(Xh, Mh, Tt, EMB, EMB, 1.0f, nullptr,
                     byT * 128, bxT * 128, bxT);
        signal_cnt(&cnt[1 + byT]);
    } else if (bid < 576) {
        // Vt = Wv^T @ X^T  (1024x4096, K=1024); no deps
        const int vid = bid - 320;
        const int bnV = vid & 31;          // col block over SEQ
        const int bmV = vid >> 5;          // row block over EMB (0..7)
        gemm_body<0>(Wvt, Xh, Vt, SEQ, EMB, 1.0f, nullptr,
                     bmV * 128, bnV * 128, bnV);
        signal_cnt(&cnt[33 + bmV]);
    } else if (bid < 1600) {
        // score: Sh = exp((X @ Tt^T)/32); needs Tt row-block bx
        const int sid = bid - 576;
        const int bx = sid & 31, by = sid >> 5;
        wait_cnt(&cnt[1 + bx], 8u);
        gemm_body<1>(Xh, Tt, Sh, SEQ, EMB, 0.03125f, part,
                     by * 128, bx * 128, bx);
        signal_cnt(&cnt[41 + by]);
    } else {
        // pv: out = diag(1/rowsum) (Sh @ Vt^T); needs score row-block + Vt block
        const int pid = bid - 1600;
        const int bx = pid & 7, by = pid >> 3;
        wait_cnt(&cnt[41 + by], 32u);
        wait_cnt(&cnt[33 + bx], 32u);
        gemm_body<2>(Sh, Vt, out, EMB, SEQ, 1.0f, part,
                     by * 128, bx * 128, bx);
    }
}

// ---------------------------------------------------------------------------
// Fused prep: z=0 convert Wq; z=1 convert Wk; z=2 transpose Wv; z=3 convert x.
// grid (32, 32, 4), block (32, 8).
// ---------------------------------------------------------------------------
__global__ void __launch_bounds__(256) prep_k(
    const float* __restrict__ x,
    const float* __restrict__ Wq, const float* __restrict__ Wk,
    const float* __restrict__ Wv,
    __half* __restrict__ Xh,
    __half* __restrict__ Wqh, __half* __restrict__ Wkh,
    __half* __restrict__ Wvt)
{
    const int z = blockIdx.z;
    const int xx = threadIdx.x, yy = threadIdx.y;   // 32 x 8

    if (z == 3) {
        const int bx = blockIdx.x * 32, by = blockIdx.y * 128;
        #pragma unroll
        for (int j = 0; j < 16; j++) {
            const int row = by + yy + j * 8;
            const int col = bx + xx;
            Xh[(size_t)row * EMB + col] =
                __float2half(x[(size_t)row * EMB + col]);
        }
        return;
    }
    if (z == 2) {
        __shared__ float tbuf[32][33];
        const int bx = blockIdx.x * 32, by = blockIdx.y * 32;
        #pragma unroll
        for (int j = 0; j < 32; j += 8)
            tbuf[yy + j][xx] = Wv[(size_t)(by + yy + j) * EMB + bx + xx];
        __syncthreads();
        #pragma unroll
        for (int j = 0; j < 32; j += 8)
            Wvt[(size_t)(bx + yy + j) * EMB + by + xx] =
                __float2half(tbuf[xx][yy + j]);
        return;
    }
    const float* in = (z == 0) ? Wq : Wk;
    __half*     out = (z == 0) ? Wqh : Wkh;
    const int bx = blockIdx.x * 32, by = blockIdx.y * 32;
    #pragma unroll
    for (int j = 0; j < 4; j++) {
        const int row = by + yy + j * 8;
        out[(size_t)row * EMB + bx + xx] =
            __float2half(in[(size_t)row * EMB + bx + xx]);
    }
}

// ---------------------------------------------------------------------------
extern "C" void kernel_launch(void* const* d_in, const int* in_sizes, int n_in,
                              void* d_out, int out_size)
{
    const float* x  = (const float*)d_in[0];
    const float* Wq = (const float*)d_in[1];
    const float* Wk = (const float*)d_in[2];
    const float* Wv = (const float*)d_in[3];
    float* out = (float*)d_out;

    __half *Xh, *Wqh, *Wkh, *Wvt, *Mh, *Tt, *Vt, *Sh;
    float *Part;
    unsigned int* Cnt;
    cudaGetSymbolAddress((void**)&Xh,  g_Xh);
    cudaGetSymbolAddress((void**)&Wqh, g_Wqh);
    cudaGetSymbolAddress((void**)&Wkh, g_Wkh);
    cudaGetSymbolAddress((void**)&Wvt, g_Wvt);
    cudaGetSymbolAddress((void**)&Mh,  g_M);
    cudaGetSymbolAddress((void**)&Tt,  g_Tt);
    cudaGetSymbolAddress((void**)&Vt,  g_Vt);
    cudaGetSymbolAddress((void**)&Sh,  g_Sh);
    cudaGetSymbolAddress((void**)&Part, g_part);
    cudaGetSymbolAddress((void**)&Cnt, g_cnt);

    cudaFuncSetAttribute(mega_k,
        cudaFuncAttributeMaxDynamicSharedMemorySize, GEMM_DYNSMEM);

    // Reset readiness counters (graph-capturable async memset).
    cudaMemsetAsync(Cnt, 0, 73 * sizeof(unsigned int), 0);

    // Prep: Wq/Wk convert, Wv transpose, x convert.
    prep_k<<<dim3(32, 32, 4), dim3(32, 8)>>>(x, Wq, Wk, Wv, Xh, Wqh, Wkh, Wvt);

    // All five GEMM stages in one launch.
    mega_k<<<dim3(1856), dim3(128), GEMM_DYNSMEM>>>(
        Xh, Wqh, Wkh, Wvt, Mh, Tt, Vt, Sh, Part, out, Cnt);
}

// round 15
// speedup vs baseline: 1.0131x; 1.0131x over previous
#include <cuda_runtime.h>
#include <cuda_fp16.h>
#include <cstdint>

#define SEQ 4096
#define EMB 1024

// ---------------- scratch (static, allocation-free) ----------------
__device__ __half g_Xh [(size_t)SEQ * EMB];
__device__ __half g_Wqh[(size_t)EMB * EMB];   // fp16(Wq), row-major
__device__ __half g_Wkh[(size_t)EMB * EMB];   // fp16(Wk), row-major
__device__ __half g_Wvt[(size_t)EMB * EMB];   // fp16(Wv^T)
__device__ __half g_M  [(size_t)EMB * EMB];   // Wq @ Wk^T
__device__ __half g_Tt [(size_t)SEQ * EMB];   // X @ M^T
__device__ __half g_Vt [(size_t)EMB * SEQ];   // Wv^T @ X^T == V^T
__device__ __half g_Sh [(size_t)SEQ * SEQ];
__device__ float  g_part[(size_t)SEQ * 64];   // per (row, colCTA*2+wn) partials
// counters: [0]=mDone(64), [1..32]=ttReady(8), [33..40]=vtReady(32), [41..72]=ready(32)
__device__ unsigned int g_cnt[73];

// ---------------- helpers ----------------
__device__ __forceinline__ uint32_t smem_u32(const void* p) {
    return (uint32_t)__cvta_generic_to_shared(p);
}
__device__ __forceinline__ void cp16(uint32_t s, const void* g) {
    asm volatile("cp.async.cg.shared.global [%0], [%1], 16;" :: "r"(s), "l"(g));
}
__device__ __forceinline__ void cp_commit() {
    asm volatile("cp.async.commit_group;" ::: "memory");
}
template <int N>
__device__ __forceinline__ void cp_wait() {
    asm volatile("cp.async.wait_group %0;" :: "n"(N) : "memory");
}
__device__ __forceinline__ float ex2_mufu(float y) {
    float r;
    asm("ex2.approx.ftz.f32 %0, %1;" : "=f"(r) : "f"(y));
    return r;
}
// exact-split exp2 on the FMA pipe (y = n + f, f in [-.5,.5], degree-5 poly)
__device__ __forceinline__ float ex2_fma(float y) {
    const float MAGIC = 12582912.0f;          // 1.5 * 2^23
    float tm = __fadd_rn(y, MAGIC);
    float f  = __fadd_rn(y, -__fadd_rn(tm, -MAGIC));
    int   eb = (__float_as_int(tm) << 23) + 0x3F800000;
    float pl = 0.0013333558f;
    pl = fmaf(pl, f, 0.0096181291f);
    pl = fmaf(pl, f, 0.0555041087f);
    pl = fmaf(pl, f, 0.2402265069f);
    pl = fmaf(pl, f, 0.6931471806f);
    pl = fmaf(pl, f, 1.0f);
    return __int_as_float(eb) * pl;
}
// m16n8k16 fp16 MMA, fp32 accumulate
__device__ __forceinline__ void mma_f16(
    float& c0, float& c1, float& c2, float& c3,
    uint32_t a0, uint32_t a1, uint32_t a2, uint32_t a3,
    uint32_t b0, uint32_t b1)
{
    asm volatile(
        "mma.sync.aligned.m16n8k16.row.col.f32.f16.f16.f32 "
        "{%0,%1,%2,%3}, {%4,%5,%6,%7}, {%8,%9}, {%0,%1,%2,%3};"
        : "+f"(c0), "+f"(c1), "+f"(c2), "+f"(c3)
        : "r"(a0), "r"(a1), "r"(a2), "r"(a3), "r"(b0), "r"(b1));
}

// spin until counter >= target, then acquire-fence + block barrier
__device__ __forceinline__ void wait_cnt(unsigned int* c, unsigned int target) {
    if (threadIdx.x == 0) {
        while (atomicAdd(c, 0u) < target) __nanosleep(100);
        __threadfence();
    }
    __syncthreads();
}
// release: fence all threads' stores, then bump counter
__device__ __forceinline__ void signal_cnt(unsigned int* c) {
    __threadfence();
    __syncthreads();
    if (threadIdx.x == 0) atomicAdd(c, 1u);
}

// ---------------------------------------------------------------------------
// FP16 tensor-core NT GEMM: C[M,N] = f( A[M,K] @ B[N,K]^T )
// 128 threads (4 warps 2x2), warp tile 64x64, CTA tile 128x128, BK=64,
// 3-stage cp.async, one __syncthreads/iter, XOR-swizzled smem,
// scalar-LDS fragment loads (known-good mainloop).
// MODE 0: fp16 out
// MODE 1: Sh = fp16(exp(alpha*acc)); per-(row,warp) partial sums -> part
// MODE 2: fp32 out scaled by rsum computed in prologue from part
// ---------------------------------------------------------------------------
#define STG 3
#define OPW (128 * 32)                 // fp16x2 words per operand tile (16KB)
#define STW (2 * OPW)
#define GEMM_DYNSMEM (STG * STW * 4)   // 98304 bytes

template <int MODE>
__device__ __forceinline__ void gemm_body(
    const __half* __restrict__ A, const __half* __restrict__ B,
    void* __restrict__ Cv, int N, int K, float alpha,
    float* __restrict__ part, int bm, int bn, int bx)
{
    extern __shared__ uint32_t sm[];
    __shared__ float rsm[128];

    const int tid  = threadIdx.x;
    const int warp = tid >> 5;
    const int lane = tid & 31;
    const int g    = lane >> 2;
    const int t    = lane & 3;
    const int wm   = warp & 1;      // 2 x 64 rows
    const int wn   = warp >> 1;     // 2 x 64 cols

    // MODE 2 prologue: reciprocal row sums for this CTA's 128 rows
    // (fixed-order 64-term sum -> deterministic). Covered by iter-0 barrier.
    if (MODE == 2) {
        const float4* pp = reinterpret_cast<const float4*>(
            part + (size_t)(bm + tid) * 64);
        float s = 0.0f;
        #pragma unroll
        for (int i = 0; i < 16; i++) {
            float4 v = pp[i];
            s += (v.x + v.y) + (v.z + v.w);
        }
        rsm[tid] = 1.0f / s;
    }

    float acc[4][8][4];
    #pragma unroll
    for (int mi = 0; mi < 4; mi++)
        #pragma unroll
        for (int ni = 0; ni < 8; ni++)
            #pragma unroll
            for (int r = 0; r < 4; r++) acc[mi][ni][r] = 0.0f;

    const uint32_t smb = smem_u32(sm);
    const int lrow = tid >> 3;          // 0..15, 8 passes -> 128 rows
    const int lseg = tid & 7;

    auto load_stage = [&](int chunk) {
        const int s  = chunk % STG;
        const int k0 = chunk * 64;
        const uint32_t sa = smb + s * (STW * 4);
        const uint32_t sb = sa + OPW * 4;
        #pragma unroll
        for (int p = 0; p < 8; p++) {
            const int row  = lrow + p * 16;
            const int segS = lseg ^ (row & 7);
            const uint32_t so = (uint32_t)(row * 128 + segS * 16);
            cp16(sa + so, A + (size_t)(bm + row) * K + k0 + lseg * 8);
            cp16(sb + so, B + (size_t)(bn + row) * K + k0 + lseg * 8);
        }
        cp_commit();
    };

    const int NT = K >> 6;

    load_stage(0);
    load_stage(1);

    for (int i = 0; i < NT; i++) {
        const int s = i % STG;
        cp_wait<1>();
        __syncthreads();

        if (i + 2 < NT) load_stage(i + 2);
        else            cp_commit();

        const uint32_t* As  = sm + s * STW;
        const uint32_t* Bsm = As + OPW;
        const int swz = 4 * g;

        #pragma unroll
        for (int ksi = 0; ksi < 4; ksi++) {
            const int c0 = (ksi * 8 + t)     ^ swz;
            const int c2 = (ksi * 8 + t + 4) ^ swz;

            uint32_t af[4][4];
            #pragma unroll
            for (int mi = 0; mi < 4; mi++) {
                const uint32_t* base = As + (wm * 64 + mi * 16 + g) * 32;
                af[mi][0] = base[c0];
                af[mi][1] = base[8 * 32 + c0];
                af[mi][2] = base[c2];
                af[mi][3] = base[8 * 32 + c2];
            }
            uint32_t bf[8][2];
            #pragma unroll
            for (int ni = 0; ni < 8; ni++) {
                const uint32_t* base = Bsm + (wn * 64 + ni * 8 + g) * 32;
                bf[ni][0] = base[c0];
                bf[ni][1] = base[c2];
            }
            #pragma unroll
            for (int mi = 0; mi < 4; mi++)
                #pragma unroll
                for (int ni = 0; ni < 8; ni++)
                    mma_f16(acc[mi][ni][0], acc[mi][ni][1],
                            acc[mi][ni][2], acc[mi][ni][3],
                            af[mi][0], af[mi][1], af[mi][2], af[mi][3],
                            bf[ni][0], bf[ni][1]);
        }
    }

    // ---- epilogue ----
    if (MODE == 0) {
        __half* C = (__half*)Cv;
        #pragma unroll
        for (int mi = 0; mi < 4; mi++) {
            const int row = bm + wm * 64 + mi * 16 + g;
            #pragma unroll
            for (int ni = 0; ni < 8; ni++) {
                const int col = bn + wn * 64 + ni * 8 + 2 * t;
                *reinterpret_cast<__half2*>(&C[(size_t)row * N + col]) =
                    __floats2half2_rn(acc[mi][ni][0], acc[mi][ni][1]);
                *reinterpret_cast<__half2*>(&C[(size_t)(row + 8) * N + col]) =
                    __floats2half2_rn(acc[mi][ni][2], acc[mi][ni][3]);
            }
        }
    } else if (MODE == 1) {
        __half* C = (__half*)Cv;
        const float aL = alpha * 1.4426950408889634f;   // alpha * log2(e)
        #pragma unroll
        for (int mi = 0; mi < 4; mi++) {
            const int row = bm + wm * 64 + mi * 16 + g;
            float sr0 = 0.0f, sr1 = 0.0f;
            #pragma unroll
            for (int ni = 0; ni < 8; ni++) {
                const int col = bn + wn * 64 + ni * 8 + 2 * t;
                float v0, v1, v2, v3;
                if (ni & 1) {                 // FMA pipe
                    v0 = ex2_fma(acc[mi][ni][0] * aL);
                    v1 = ex2_fma(acc[mi][ni][1] * aL);
                    v2 = ex2_fma(acc[mi][ni][2] * aL);
                    v3 = ex2_fma(acc[mi][ni][3] * aL);
                } else {                      // MUFU pipe
                    v0 = ex2_mufu(acc[mi][ni][0] * aL);
                    v1 = ex2_mufu(acc[mi][ni][1] * aL);
                    v2 = ex2_mufu(acc[mi][ni][2] * aL);
                    v3 = ex2_mufu(acc[mi][ni][3] * aL);
                }
                *reinterpret_cast<__half2*>(&C[(size_t)row * N + col]) =
                    __floats2half2_rn(v0, v1);
                *reinterpret_cast<__half2*>(&C[(size_t)(row + 8) * N + col]) =
                    __floats2half2_rn(v2, v3);
                sr0 += v0 + v1;
                sr1 += v2 + v3;
            }
            // sum over the 4 t-lanes (same g)
            sr0 += __shfl_xor_sync(0xFFFFFFFF, sr0, 1);
            sr0 += __shfl_xor_sync(0xFFFFFFFF, sr0, 2);
            sr1 += __shfl_xor_sync(0xFFFFFFFF, sr1, 1);
            sr1 += __shfl_xor_sync(0xFFFFFFFF, sr1, 2);
            if (t == 0) {
                part[(size_t)row * 64 + bx * 2 + wn]       = sr0;
                part[(size_t)(row + 8) * 64 + bx * 2 + wn] = sr1;
            }
        }
    } else {
        float* C = (float*)Cv;
        #pragma unroll
        for (int mi = 0; mi < 4; mi++) {
            const int lr  = wm * 64 + mi * 16 + g;
            const int row = bm + lr;
            const float s0 = rsm[lr];
            const float s1 = rsm[lr + 8];
            #pragma unroll
            for (int ni = 0; ni < 8; ni++) {
                const int col = bn + wn * 64 + ni * 8 + 2 * t;
                *reinterpret_cast<float2*>(&C[(size_t)row * N + col]) =
                    make_float2(acc[mi][ni][0] * s0, acc[mi][ni][1] * s0);
                *reinterpret_cast<float2*>(&C[(size_t)(row + 8) * N + col]) =
                    make_float2(acc[mi][ni][2] * s1, acc[mi][ni][3] * s1);
            }
        }
    }
}

// ---------------------------------------------------------------------------
// Mega kernel: all 5 GEMM stages in one launch, gated by readiness counters.
// Stage order chosen so the FIRST resident wave does only dependency-free
// work (M + Vt), with Tt/score/pv back-filling. All waits point strictly
// from higher bid to lower bid (dispatch order) -> guaranteed progress.
//   bid 0..63     : M  = Wq @ Wk^T                    -> cnt[0]        (64)
//   bid 64..319   : Vt = Wv^T @ X^T   (no deps)       -> cnt[33+bmV]   (32)
//   bid 320..575  : Tt = X @ M^T      (waits M)       -> cnt[1+byT]    (8)
//   bid 576..1599 : score (exp)       (waits Tt blk)  -> cnt[41+by]    (32)
//   bid 1600..1855: pv                (waits score row-block + Vt block)
// ---------------------------------------------------------------------------
__global__ void __launch_bounds__(128, 2) mega_k(
    const __half* __restrict__ Xh,
    const __half* __restrict__ Wqh, const __half* __restrict__ Wkh,
    const __half* __restrict__ Wvt,
    __half* __restrict__ Mh, __half* __restrict__ Tt,
    __half* __restrict__ Vt, __half* __restrict__ Sh,
    float* __restrict__ part, float* __restrict__ out,
    unsigned int* __restrict__ cnt)
{
    const int bid = blockIdx.x;

    if (bid < 64) {
        // M = Wq @ Wk^T  (1024x1024, K=1024)
        const int bx = bid & 7, by = bid >> 3;
        gemm_body<0>(Wqh, Wkh, Mh, EMB, EMB, 1.0f, nullptr,
                     by * 128, bx * 128, bx);
        signal_cnt(&cnt[0]);
    } else if (bid < 320) {
        // Vt = Wv^T @ X^T  (1024x4096, K=1024); no deps
        const int vid = bid - 64;
        const int bnV = vid & 31;          // col block over SEQ
        const int bmV = vid >> 5;          // row block over EMB (0..7)
        gemm_body<0>(Wvt, Xh, Vt, SEQ, EMB, 1.0f, nullptr,
                     bmV * 128, bnV * 128, bnV);
        signal_cnt(&cnt[33 + bmV]);
    } else if (bid < 576) {
        // Tt = X @ M^T  (4096x1024, K=1024); needs all of M
        const int tidx = bid - 320;
        const int bxT = tidx & 7;          // col block over 1024
        const int byT = tidx >> 3;         // row block over SEQ (0..31)
        wait_cnt(&cnt[0], 64u);
        gemm_body<0>(Xh, Mh, Tt, EMB, EMB, 1.0f, nullptr,
                     byT * 128, bxT * 128, bxT);
        signal_cnt(&cnt[1 + byT]);
    } else if (bid < 1600) {
        // score: Sh = exp((X @ Tt^T)/32); needs Tt row-block bx
        const int sid = bid - 576;
        const int bx = sid & 31, by = sid >> 5;
        wait_cnt(&cnt[1 + bx], 8u);
        gemm_body<1>(Xh, Tt, Sh, SEQ, EMB, 0.03125f, part,
                     by * 128, bx * 128, bx);
        signal_cnt(&cnt[41 + by]);
    } else {
        // pv: out = diag(1/rowsum) (Sh @ Vt^T); needs score row-block + Vt block
        const int pid = bid - 1600;
        const int bx = pid & 7, by = pid >> 3;
        wait_cnt(&cnt[41 + by], 32u);
        wait_cnt(&cnt[33 + bx], 32u);
        gemm_body<2>(Sh, Vt, out, EMB, SEQ, 1.0f, part,
                     by * 128, bx * 128, bx);
    }
}

// ---------------------------------------------------------------------------
// Fused prep: z=0 convert Wq; z=1 convert Wk; z=2 transpose Wv; z=3 convert x.
// grid (32, 32, 4), block (32, 8).
// ---------------------------------------------------------------------------
__global__ void __launch_bounds__(256) prep_k(
    const float* __restrict__ x,
    const float* __restrict__ Wq, const float* __restrict__ Wk,
    const float* __restrict__ Wv,
    __half* __restrict__ Xh,
    __half* __restrict__ Wqh, __half* __restrict__ Wkh,
    __half* __restrict__ Wvt)
{
    const int z = blockIdx.z;
    const int xx = threadIdx.x, yy = threadIdx.y;   // 32 x 8

    if (z == 3) {
        const int bx = blockIdx.x * 32, by = blockIdx.y * 128;
        #pragma unroll
        for (int j = 0; j < 16; j++) {
            const int row = by + yy + j * 8;
            const int col = bx + xx;
            Xh[(size_t)row * EMB + col] =
                __float2half(x[(size_t)row * EMB + col]);
        }
        return;
    }
    if (z == 2) {
        __shared__ float tbuf[32][33];
        const int bx = blockIdx.x * 32, by = blockIdx.y * 32;
        #pragma unroll
        for (int j = 0; j < 32; j += 8)
            tbuf[yy + j][xx] = Wv[(size_t)(by + yy + j) * EMB + bx + xx];
        __syncthreads();
        #pragma unroll
        for (int j = 0; j < 32; j += 8)
            Wvt[(size_t)(bx + yy + j) * EMB + by + xx] =
                __float2half(tbuf[xx][yy + j]);
        return;
    }
    const float* in = (z == 0) ? Wq : Wk;
    __half*     out = (z == 0) ? Wqh : Wkh;
    const int bx = blockIdx.x * 32, by = blockIdx.y * 32;
    #pragma unroll
    for (int j = 0; j < 4; j++) {
        const int row = by + yy + j * 8;
        out[(size_t)row * EMB + bx + xx] =
            __float2half(in[(size_t)row * EMB + bx + xx]);
    }
}

// ---------------------------------------------------------------------------
extern "C" void kernel_launch(void* const* d_in, const int* in_sizes, int n_in,
                              void* d_out, int out_size)
{
    const float* x  = (const float*)d_in[0];
    const float* Wq = (const float*)d_in[1];
    const float* Wk = (const float*)d_in[2];
    const float* Wv = (const float*)d_in[3];
    float* out = (float*)d_out;

    __half *Xh, *Wqh, *Wkh, *Wvt, *Mh, *Tt, *Vt, *Sh;
    float *Part;
    unsigned int* Cnt;
    cudaGetSymbolAddress((void**)&Xh,  g_Xh);
    cudaGetSymbolAddress((void**)&Wqh, g_Wqh);
    cudaGetSymbolAddress((void**)&Wkh, g_Wkh);
    cudaGetSymbolAddress((void**)&Wvt, g_Wvt);
    cudaGetSymbolAddress((void**)&Mh,  g_M);
    cudaGetSymbolAddress((void**)&Tt,  g_Tt);
    cudaGetSymbolAddress((void**)&Vt,  g_Vt);
    cudaGetSymbolAddress((void**)&Sh,  g_Sh);
    cudaGetSymbolAddress((void**)&Part, g_part);
    cudaGetSymbolAddress((void**)&Cnt, g_cnt);

    cudaFuncSetAttribute(mega_k,
        cudaFuncAttributeMaxDynamicSharedMemorySize, GEMM_DYNSMEM);

    // Reset readiness counters (graph-capturable async memset).
    cudaMemsetAsync(Cnt, 0, 73 * sizeof(unsigned int), 0);

    // Prep: Wq/Wk convert, Wv transpose, x convert.
    prep_k<<<dim3(32, 32, 4), dim3(32, 8)>>>(x, Wq, Wk, Wv, Xh, Wqh, Wkh, Wvt);

    // All five GEMM stages in one launch.
    mega_k<<<dim3(1856), dim3(128), GEMM_DYNSMEM>>>(
        Xh, Wqh, Wkh, Wvt, Mh, Tt, Vt, Sh, Part, out, Cnt);
}

// round 16
// speedup vs baseline: 1.0238x; 1.0105x over previous
#include <cuda_runtime.h>
#include <cuda_fp16.h>
#include <cstdint>

#define SEQ 4096
#define EMB 1024

// ---------------- scratch (static, allocation-free) ----------------
__device__ __half g_Xh [(size_t)SEQ * EMB];
__device__ __half g_Wqh[(size_t)EMB * EMB];   // fp16(Wq), row-major
__device__ __half g_Wkh[(size_t)EMB * EMB];   // fp16(Wk), row-major
__device__ __half g_Wvt[(size_t)EMB * EMB];   // fp16(Wv^T)
__device__ __half g_M  [(size_t)EMB * EMB];   // Wq @ Wk^T
__device__ __half g_Tt [(size_t)SEQ * EMB];   // NT(X, M)  (score K-operand)
__device__ __half g_Vt [(size_t)EMB * SEQ];   // NT(Wv^T, X) == V^T
__device__ __half g_Sh [(size_t)SEQ * SEQ];
__device__ float  g_part[(size_t)SEQ * 64];   // per (row, colCTA*2+wn) partials
__device__ unsigned int g_ready[32];          // per row-block completion count

// ---------------- helpers ----------------
__device__ __forceinline__ uint32_t smem_u32(const void* p) {
    return (uint32_t)__cvta_generic_to_shared(p);
}
__device__ __forceinline__ void cp16(uint32_t s, const void* g) {
    asm volatile("cp.async.cg.shared.global [%0], [%1], 16;" :: "r"(s), "l"(g));
}
__device__ __forceinline__ void cp_commit() {
    asm volatile("cp.async.commit_group;" ::: "memory");
}
template <int N>
__device__ __forceinline__ void cp_wait() {
    asm volatile("cp.async.wait_group %0;" :: "n"(N) : "memory");
}
__device__ __forceinline__ float ex2_mufu(float y) {
    float r;
    asm("ex2.approx.ftz.f32 %0, %1;" : "=f"(r) : "f"(y));
    return r;
}
// exact-split exp2 on the FMA pipe (y = n + f, f in [-.5,.5], degree-5 poly)
__device__ __forceinline__ float ex2_fma(float y) {
    const float MAGIC = 12582912.0f;          // 1.5 * 2^23
    float tm = __fadd_rn(y, MAGIC);
    float f  = __fadd_rn(y, -__fadd_rn(tm, -MAGIC));
    int   eb = (__float_as_int(tm) << 23) + 0x3F800000;
    float pl = 0.0013333558f;
    pl = fmaf(pl, f, 0.0096181291f);
    pl = fmaf(pl, f, 0.0555041087f);
    pl = fmaf(pl, f, 0.2402265069f);
    pl = fmaf(pl, f, 0.6931471806f);
    pl = fmaf(pl, f, 1.0f);
    return __int_as_float(eb) * pl;
}
// m16n8k16 fp16 MMA, fp32 accumulate
__device__ __forceinline__ void mma_f16(
    float& c0, float& c1, float& c2, float& c3,
    uint32_t a0, uint32_t a1, uint32_t a2, uint32_t a3,
    uint32_t b0, uint32_t b1)
{
    asm volatile(
        "mma.sync.aligned.m16n8k16.row.col.f32.f16.f16.f32 "
        "{%0,%1,%2,%3}, {%4,%5,%6,%7}, {%8,%9}, {%0,%1,%2,%3};"
        : "+f"(c0), "+f"(c1), "+f"(c2), "+f"(c3)
        : "r"(a0), "r"(a1), "r"(a2), "r"(a3), "r"(b0), "r"(b1));
}

// ---------------------------------------------------------------------------
// FP16 tensor-core NT GEMM: C[M,N] = f( A[M,K] @ B[N,K]^T )
// 128 threads (4 warps 2x2), warp tile 64x64, CTA tile 128x128, BK=64,
// 3-stage cp.async, one __syncthreads/iter, XOR-swizzled smem,
// scalar-LDS fragment loads (known-good mainloop).
// MODE 0: fp16 out
// MODE 1: Sh = fp16(exp(alpha*acc)); per-(row,warp) partial sums -> part
// MODE 2: fp32 out scaled by rsum computed in prologue from part
// ---------------------------------------------------------------------------
#define STG 3
#define OPW (128 * 32)                 // fp16x2 words per operand tile (16KB)
#define STW (2 * OPW)
#define GEMM_DYNSMEM (STG * STW * 4)   // 98304 bytes

template <int MODE>
__device__ __forceinline__ void gemm_body(
    const __half* __restrict__ A, const __half* __restrict__ B,
    void* __restrict__ Cv, int N, int K, float alpha,
    float* __restrict__ part, int bm, int bn, int bx)
{
    extern __shared__ uint32_t sm[];
    __shared__ float rsm[128];

    const int tid  = threadIdx.x;
    const int warp = tid >> 5;
    const int lane = tid & 31;
    const int g    = lane >> 2;
    const int t    = lane & 3;
    const int wm   = warp & 1;      // 2 x 64 rows
    const int wn   = warp >> 1;     // 2 x 64 cols

    // MODE 2 prologue: reciprocal row sums for this CTA's 128 rows
    // (fixed-order 64-term sum -> deterministic). Covered by iter-0 barrier.
    if (MODE == 2) {
        const float4* pp = reinterpret_cast<const float4*>(
            part + (size_t)(bm + tid) * 64);
        float s = 0.0f;
        #pragma unroll
        for (int i = 0; i < 16; i++) {
            float4 v = pp[i];
            s += (v.x + v.y) + (v.z + v.w);
        }
        rsm[tid] = 1.0f / s;
    }

    float acc[4][8][4];
    #pragma unroll
    for (int mi = 0; mi < 4; mi++)
        #pragma unroll
        for (int ni = 0; ni < 8; ni++)
            #pragma unroll
            for (int r = 0; r < 4; r++) acc[mi][ni][r] = 0.0f;

    const uint32_t smb = smem_u32(sm);
    const int lrow = tid >> 3;          // 0..15, 8 passes -> 128 rows
    const int lseg = tid & 7;

    auto load_stage = [&](int chunk) {
        const int s  = chunk % STG;
        const int k0 = chunk * 64;
        const uint32_t sa = smb + s * (STW * 4);
        const uint32_t sb = sa + OPW * 4;
        #pragma unroll
        for (int p = 0; p < 8; p++) {
            const int row  = lrow + p * 16;
            const int segS = lseg ^ (row & 7);
            const uint32_t so = (uint32_t)(row * 128 + segS * 16);
            cp16(sa + so, A + (size_t)(bm + row) * K + k0 + lseg * 8);
            cp16(sb + so, B + (size_t)(bn + row) * K + k0 + lseg * 8);
        }
        cp_commit();
    };

    const int NT = K >> 6;

    load_stage(0);
    load_stage(1);

    for (int i = 0; i < NT; i++) {
        const int s = i % STG;
        cp_wait<1>();
        __syncthreads();

        if (i + 2 < NT) load_stage(i + 2);
        else            cp_commit();

        const uint32_t* As  = sm + s * STW;
        const uint32_t* Bsm = As + OPW;
        const int swz = 4 * g;

        #pragma unroll
        for (int ksi = 0; ksi < 4; ksi++) {
            const int c0 = (ksi * 8 + t)     ^ swz;
            const int c2 = (ksi * 8 + t + 4) ^ swz;

            uint32_t af[4][4];
            #pragma unroll
            for (int mi = 0; mi < 4; mi++) {
                const uint32_t* base = As + (wm * 64 + mi * 16 + g) * 32;
                af[mi][0] = base[c0];
                af[mi][1] = base[8 * 32 + c0];
                af[mi][2] = base[c2];
                af[mi][3] = base[8 * 32 + c2];
            }
            uint32_t bf[8][2];
            #pragma unroll
            for (int ni = 0; ni < 8; ni++) {
                const uint32_t* base = Bsm + (wn * 64 + ni * 8 + g) * 32;
                bf[ni][0] = base[c0];
                bf[ni][1] = base[c2];
            }
            #pragma unroll
            for (int mi = 0; mi < 4; mi++)
                #pragma unroll
                for (int ni = 0; ni < 8; ni++)
                    mma_f16(acc[mi][ni][0], acc[mi][ni][1],
                            acc[mi][ni][2], acc[mi][ni][3],
                            af[mi][0], af[mi][1], af[mi][2], af[mi][3],
                            bf[ni][0], bf[ni][1]);
        }
    }

    // ---- epilogue ----
    if (MODE == 0) {
        __half* C = (__half*)Cv;
        #pragma unroll
        for (int mi = 0; mi < 4; mi++) {
            const int row = bm + wm * 64 + mi * 16 + g;
            #pragma unroll
            for (int ni = 0; ni < 8; ni++) {
                const int col = bn + wn * 64 + ni * 8 + 2 * t;
                *reinterpret_cast<__half2*>(&C[(size_t)row * N + col]) =
                    __floats2half2_rn(acc[mi][ni][0], acc[mi][ni][1]);
                *reinterpret_cast<__half2*>(&C[(size_t)(row + 8) * N + col]) =
                    __floats2half2_rn(acc[mi][ni][2], acc[mi][ni][3]);
            }
        }
    } else if (MODE == 1) {
        __half* C = (__half*)Cv;
        const float aL = alpha * 1.4426950408889634f;   // alpha * log2(e)
        #pragma unroll
        for (int mi = 0; mi < 4; mi++) {
            const int row = bm + wm * 64 + mi * 16 + g;
            float sr0 = 0.0f, sr1 = 0.0f;
            #pragma unroll
            for (int ni = 0; ni < 8; ni++) {
                const int col = bn + wn * 64 + ni * 8 + 2 * t;
                float v0, v1, v2, v3;
                if (ni & 1) {                 // FMA pipe
                    v0 = ex2_fma(acc[mi][ni][0] * aL);
                    v1 = ex2_fma(acc[mi][ni][1] * aL);
                    v2 = ex2_fma(acc[mi][ni][2] * aL);
                    v3 = ex2_fma(acc[mi][ni][3] * aL);
                } else {                      // MUFU pipe
                    v0 = ex2_mufu(acc[mi][ni][0] * aL);
                    v1 = ex2_mufu(acc[mi][ni][1] * aL);
                    v2 = ex2_mufu(acc[mi][ni][2] * aL);
                    v3 = ex2_mufu(acc[mi][ni][3] * aL);
                }
                *reinterpret_cast<__half2*>(&C[(size_t)row * N + col]) =
                    __floats2half2_rn(v0, v1);
                *reinterpret_cast<__half2*>(&C[(size_t)(row + 8) * N + col]) =
                    __floats2half2_rn(v2, v3);
                sr0 += v0 + v1;
                sr1 += v2 + v3;
            }
            // sum over the 4 t-lanes (same g)
            sr0 += __shfl_xor_sync(0xFFFFFFFF, sr0, 1);
            sr0 += __shfl_xor_sync(0xFFFFFFFF, sr0, 2);
            sr1 += __shfl_xor_sync(0xFFFFFFFF, sr1, 1);
            sr1 += __shfl_xor_sync(0xFFFFFFFF, sr1, 2);
            if (t == 0) {
                part[(size_t)row * 64 + bx * 2 + wn]       = sr0;
                part[(size_t)(row + 8) * 64 + bx * 2 + wn] = sr1;
            }
        }
    } else {
        float* C = (float*)Cv;
        #pragma unroll
        for (int mi = 0; mi < 4; mi++) {
            const int lr  = wm * 64 + mi * 16 + g;
            const int row = bm + lr;
            const float s0 = rsm[lr];
            const float s1 = rsm[lr + 8];
            #pragma unroll
            for (int ni = 0; ni < 8; ni++) {
                const int col = bn + wn * 64 + ni * 8 + 2 * t;
                *reinterpret_cast<float2*>(&C[(size_t)row * N + col]) =
                    make_float2(acc[mi][ni][0] * s0, acc[mi][ni][1] * s0);
                *reinterpret_cast<float2*>(&C[(size_t)(row + 8) * N + col]) =
                    make_float2(acc[mi][ni][2] * s1, acc[mi][ni][3] * s1);
            }
        }
    }
}

// Plain fp16-out NT GEMM (M, Tt, Vt).
__global__ void __launch_bounds__(128, 2) gemm16_k(
    const __half* __restrict__ A, const __half* __restrict__ B,
    __half* __restrict__ C, int N, int K)
{
    gemm_body<0>(A, B, C, N, K, 1.0f, nullptr,
                 blockIdx.y * 128, blockIdx.x * 128, blockIdx.x);
}

// ---------------------------------------------------------------------------
// Fused score+PV kernel with row-block readiness counters (r13-validated).
// bid < 1024 : score role — S tile (exp, partial sums), then signal ready[by].
// bid >= 1024: pv role — spin until ready[by]==32, then PV tile.
// 256 pv CTAs < residency slots -> score always has slots -> no deadlock.
// ---------------------------------------------------------------------------
__global__ void __launch_bounds__(128, 2) attn_k(
    const __half* __restrict__ Xh, const __half* __restrict__ Tt,
    __half* __restrict__ Sh, float* __restrict__ part,
    const __half* __restrict__ Vt, float* __restrict__ out,
    unsigned int* __restrict__ ready)
{
    const int bid = blockIdx.x;
    if (bid < 1024) {
        const int bx = bid & 31, by = bid >> 5;
        gemm_body<1>(Xh, Tt, Sh, SEQ, EMB, 0.03125f, part,
                     by * 128, bx * 128, bx);
        __threadfence();
        __syncthreads();
        if (threadIdx.x == 0) atomicAdd(&ready[by], 1u);
    } else {
        const int pid = bid - 1024;
        const int bx = pid & 7, by = pid >> 3;
        if (threadIdx.x == 0) {
            while (atomicAdd(&ready[by], 0u) < 32u) __nanosleep(200);
            __threadfence();
        }
        __syncthreads();
        gemm_body<2>(Sh, Vt, out, EMB, SEQ, 1.0f, part,
                     by * 128, bx * 128, bx);
    }
}

// ---------------------------------------------------------------------------
// prepW: convert Wq (z=0), Wk (z=1) to fp16. grid (32, 32, 2), block (32, 8).
// ---------------------------------------------------------------------------
__global__ void __launch_bounds__(256) prepW_k(
    const float* __restrict__ Wq, const float* __restrict__ Wk,
    __half* __restrict__ Wqh, __half* __restrict__ Wkh)
{
    const int z = blockIdx.z;
    const int xx = threadIdx.x, yy = threadIdx.y;
    const float* in = (z == 0) ? Wq : Wk;
    __half*     out = (z == 0) ? Wqh : Wkh;
    const int bx = blockIdx.x * 32, by = blockIdx.y * 32;
    #pragma unroll
    for (int j = 0; j < 4; j++) {
        const int row = by + yy + j * 8;
        out[(size_t)row * EMB + bx + xx] =
            __float2half(in[(size_t)row * EMB + bx + xx]);
    }
}

// ---------------------------------------------------------------------------
// prepXV: z=0 transpose+convert Wv; z=1 convert x. grid (32, 32, 2).
// ---------------------------------------------------------------------------
__global__ void __launch_bounds__(256) prepXV_k(
    const float* __restrict__ x, const float* __restrict__ Wv,
    __half* __restrict__ Xh, __half* __restrict__ Wvt)
{
    const int z = blockIdx.z;
    const int xx = threadIdx.x, yy = threadIdx.y;

    if (z == 1) {
        const int bx = blockIdx.x * 32, by = blockIdx.y * 128;
        #pragma unroll
        for (int j = 0; j < 16; j++) {
            const int row = by + yy + j * 8;
            const int col = bx + xx;
            Xh[(size_t)row * EMB + col] =
                __float2half(x[(size_t)row * EMB + col]);
        }
        return;
    }
    __shared__ float tbuf[32][33];
    const int bx = blockIdx.x * 32, by = blockIdx.y * 32;
    #pragma unroll
    for (int j = 0; j < 32; j += 8)
        tbuf[yy + j][xx] = Wv[(size_t)(by + yy + j) * EMB + bx + xx];
    __syncthreads();
    #pragma unroll
    for (int j = 0; j < 32; j += 8)
        Wvt[(size_t)(bx + yy + j) * EMB + by + xx] =
            __float2half(tbuf[xx][yy + j]);
}

// ---------------------------------------------------------------------------
extern "C" void kernel_launch(void* const* d_in, const int* in_sizes, int n_in,
                              void* d_out, int out_size)
{
    const float* x  = (const float*)d_in[0];
    const float* Wq = (const float*)d_in[1];
    const float* Wk = (const float*)d_in[2];
    const float* Wv = (const float*)d_in[3];
    float* out = (float*)d_out;

    __half *Xh, *Wqh, *Wkh, *Wvt, *Mh, *Tt, *Vt, *Sh;
    float *Part;
    unsigned int* Ready;
    cudaGetSymbolAddress((void**)&Xh,  g_Xh);
    cudaGetSymbolAddress((void**)&Wqh, g_Wqh);
    cudaGetSymbolAddress((void**)&Wkh, g_Wkh);
    cudaGetSymbolAddress((void**)&Wvt, g_Wvt);
    cudaGetSymbolAddress((void**)&Mh,  g_M);
    cudaGetSymbolAddress((void**)&Tt,  g_Tt);
    cudaGetSymbolAddress((void**)&Vt,  g_Vt);
    cudaGetSymbolAddress((void**)&Sh,  g_Sh);
    cudaGetSymbolAddress((void**)&Part, g_part);
    cudaGetSymbolAddress((void**)&Ready, g_ready);

    cudaFuncSetAttribute(gemm16_k,
        cudaFuncAttributeMaxDynamicSharedMemorySize, GEMM_DYNSMEM);
    cudaFuncSetAttribute(attn_k,
        cudaFuncAttributeMaxDynamicSharedMemorySize, GEMM_DYNSMEM);

    // Side stream + events, created once on the (uncaptured) correctness call.
    static cudaStream_t s2 = nullptr;
    static cudaEvent_t evW = nullptr, evX = nullptr, evT = nullptr;
    if (s2 == nullptr) {
        cudaStreamCreateWithFlags(&s2, cudaStreamNonBlocking);
        cudaEventCreateWithFlags(&evW, cudaEventDisableTiming);
        cudaEventCreateWithFlags(&evX, cudaEventDisableTiming);
        cudaEventCreateWithFlags(&evT, cudaEventDisableTiming);
    }

    const dim3 blk(128);

    // Reset readiness counters (graph-capturable async memset).
    cudaMemsetAsync(Ready, 0, 32 * sizeof(unsigned int), 0);

    // Prep split: weights first (M's only dependency), then x + Wv^T.
    prepW_k<<<dim3(32, 32, 2), dim3(32, 8)>>>(Wq, Wk, Wqh, Wkh);
    cudaEventRecord(evW, 0);
    prepXV_k<<<dim3(32, 32, 2), dim3(32, 8)>>>(x, Wv, Xh, Wvt);
    cudaEventRecord(evX, 0);

    // Side stream: M = Wq @ Wk^T (after evW), then Tt = NT(X, M) (after evX).
    cudaStreamWaitEvent(s2, evW, 0);
    gemm16_k<<<dim3(8, 8), blk, GEMM_DYNSMEM, s2>>>(Wqh, Wkh, Mh, EMB, EMB);
    cudaStreamWaitEvent(s2, evX, 0);
    gemm16_k<<<dim3(8, 32), blk, GEMM_DYNSMEM, s2>>>(Xh, Mh, Tt, EMB, EMB);
    cudaEventRecord(evT, s2);

    // Main stream (concurrent): Vt = NT(Wv^T, X)  (coalesced out).
    gemm16_k<<<dim3(32, 8), blk, GEMM_DYNSMEM>>>(Wvt, Xh, Vt, SEQ, EMB);

    // Join, then the fused score+PV kernel.
    cudaStreamWaitEvent(0, evT, 0);
    attn_k<<<dim3(1280), blk, GEMM_DYNSMEM>>>(Xh, Tt, Sh, Part, Vt, out, Ready);
}